// round 15
// baseline (speedup 1.0000x reference)
#include <cuda_runtime.h>
#include <cstdint>

#define BB 8
#define NN 4096
#define SS 1024
#define NSAMP 32
#define CIN 64
#define CMLP 128
#define COUT 256

// fps_prep block layout (256 threads/block): 0..7 fps, 8..72 wfuse, 73..104 clear
#define NB_FPS   8
#define B_WFUSE  8
#define B_CLEAR  73
#define GRID_FP  105
#define FPS_SMEM (NN * 3 * sizeof(float))

// ballq_gemm block layout: 0..511 ballq, 512..1535 gemm
#define NB_BALLQ 512
#define GRID_BG  1536

// packed f32x2 helpers (Blackwell FFMA2 family — PTX only; add/sub/mul/fma only!)
#define SUB_F32X2(out, a, b) \
    asm("sub.rn.f32x2 %0, %1, %2;" : "=l"(out) : "l"(a), "l"(b))
#define MUL_F32X2(out, a, b) \
    asm("mul.rn.f32x2 %0, %1, %2;" : "=l"(out) : "l"(a), "l"(b))
#define FMA_F32X2(out, a, b, c) \
    asm("fma.rn.f32x2 %0, %1, %2, %3;" : "=l"(out) : "l"(a), "l"(b), "l"(c))
#define PACK_F32X2(out, lo, hi) \
    asm("mov.b64 %0, {%1, %2};" : "=l"(out) : "f"(lo), "f"(hi))
#define UNPACK_F32X2(lo, hi, in) \
    asm("mov.b64 {%0, %1}, %2;" : "=f"(lo), "=f"(hi) : "l"(in))

// ---------------- scratch (device globals; no allocation) ----------------
__device__ float d_g[BB * NN * COUT];     // fused-MLP output per point  (33.5 MB)
__device__ float d_Wf[CIN * COUT];        // W1 @ Wc
__device__ float d_bf[COUT];              // b1 @ Wc + bc
__device__ float d_newxyz[BB * SS * 3];   // FPS-sampled centers
__device__ int   d_gidx[BB * SS * NSAMP]; // ball-query groups
__device__ int   d_cnt[BB * NN];          // per-point gather multiplicity (BN weights)
__device__ float d_sum[COUT];
__device__ float d_sumsq[COUT];

// ============ LAUNCH 1: fps (blocks 0..7) + prep (independent blocks) ============
// 256 threads. fps: 16 pts/thread; packed f32x2 distance math; scalar fminf dmin;
// value-only fmaxf tree + equality bitmask slot search (lowest slot on ties);
// (val_bits, ~idx) REDUX two-level block argmax; one bar/iter (double buffer).
__global__ void __launch_bounds__(256, 1) fps_prep_kernel(
        const float* __restrict__ xyz,
        const float* __restrict__ W1, const float* __restrict__ b1,
        const float* __restrict__ Wc, const float* __restrict__ bc) {
    extern __shared__ float sxyz[];           // 48KB (fps blocks only)
    __shared__ unsigned svh[2][8];
    __shared__ unsigned svl[2][8];
    const int bid = blockIdx.x;
    const int tid = threadIdx.x;

    if (bid >= NB_FPS) {
        if (bid < B_CLEAR) {
            // WFUSE: 65 blocks x 256 = 16640 = (CIN+1)*COUT exactly
            int idx = (bid - B_WFUSE) * 256 + tid;
            int k = idx >> 8, c = idx & 255;
            if (k < CIN) {
                float acc = 0.f;
                for (int m = 0; m < CMLP; m++) acc += W1[k * CMLP + m] * Wc[m * COUT + c];
                d_Wf[k * COUT + c] = acc;
            } else {
                float acc = bc[c];
                for (int m = 0; m < CMLP; m++) acc += b1[m] * Wc[m * COUT + c];
                d_bf[c] = acc;
            }
        } else {
            // CLEAR: 32 blocks x 256 x 4 = 32768 ints
            int g = (bid - B_CLEAR) * 256 + tid;
#pragma unroll
            for (int r = 0; r < 4; r++) d_cnt[g + r * 8192] = 0;
            if (g < COUT) { d_sum[g] = 0.f; d_sumsq[g] = 0.f; }
        }
        return;
    }

    // -------- FPS --------
    float* xs = sxyz;
    float* ys = sxyz + NN;
    float* zs = sxyz + 2 * NN;

    const int b = bid;
    const float* xb = xyz + (size_t)b * NN * 3;
    for (int k = tid; k < NN * 3; k += 256) {
        float v = xb[k];
        int i = k / 3, c = k - 3 * i;
        if (c == 0) xs[i] = v; else if (c == 1) ys[i] = v; else zs[i] = v;
    }
    __syncthreads();

    unsigned long long px2[8], py2[8], pz2[8];
    float dmin[16];
#pragma unroll
    for (int p = 0; p < 8; p++) {
        int i0 = tid + ((2 * p) << 8);       // slot 2p   (lower global idx)
        int i1 = tid + ((2 * p + 1) << 8);   // slot 2p+1
        PACK_F32X2(px2[p], xs[i0], xs[i1]);
        PACK_F32X2(py2[p], ys[i0], ys[i1]);
        PACK_F32X2(pz2[p], zs[i0], zs[i1]);
        dmin[2 * p] = 1e10f; dmin[2 * p + 1] = 1e10f;
    }

    int far = 0;
    const int lane = tid & 31, w = tid >> 5;

    for (int it = 0; it < SS; it++) {
        float cx = xs[far], cy = ys[far], cz = zs[far];   // LDS broadcast
        if (tid == 0) {
            float* nx = d_newxyz + ((size_t)b * SS + it) * 3;
            nx[0] = cx; nx[1] = cy; nx[2] = cz;
        }
        if (it == SS - 1) break;   // last step's argmax unused by reference

        unsigned long long cx2, cy2, cz2;
        PACK_F32X2(cx2, cx, cx);
        PACK_F32X2(cy2, cy, cy);
        PACK_F32X2(cz2, cz, cz);

        // packed distance, scalar dmin update (identical IEEE ops/association)
#pragma unroll
        for (int p = 0; p < 8; p++) {
            unsigned long long dx2, dy2, dz2, dd2;
            SUB_F32X2(dx2, px2[p], cx2);             // px - cx
            SUB_F32X2(dy2, py2[p], cy2);
            SUB_F32X2(dz2, pz2[p], cz2);
            MUL_F32X2(dd2, dx2, dx2);                // dx*dx
            FMA_F32X2(dd2, dy2, dy2, dd2);           // + dy*dy
            FMA_F32X2(dd2, dz2, dz2, dd2);           // + dz*dz
            float d0, d1;
            UNPACK_F32X2(d0, d1, dd2);
            dmin[2 * p]     = fminf(dmin[2 * p], d0);
            dmin[2 * p + 1] = fminf(dmin[2 * p + 1], d1);
        }

        // value-only max tree (exact: fmaxf returns one of its inputs)
        float t0 = fmaxf(dmin[0], dmin[1]),   t1 = fmaxf(dmin[2], dmin[3]);
        float t2 = fmaxf(dmin[4], dmin[5]),   t3 = fmaxf(dmin[6], dmin[7]);
        float t4 = fmaxf(dmin[8], dmin[9]),   t5 = fmaxf(dmin[10], dmin[11]);
        float t6 = fmaxf(dmin[12], dmin[13]), t7 = fmaxf(dmin[14], dmin[15]);
        float u0 = fmaxf(t0, t1), u1 = fmaxf(t2, t3);
        float u2 = fmaxf(t4, t5), u3 = fmaxf(t6, t7);
        float bv = fmaxf(fmaxf(u0, u1), fmaxf(u2, u3));   // thread max VALUE

        // equality bitmask slot search: lowest set bit = lowest slot = lowest idx
        unsigned mask = 0;
#pragma unroll
        for (int s = 0; s < 16; s++) mask |= (dmin[s] == bv) ? (1u << s) : 0u;
        int slot = __ffs(mask) - 1;
        int bi = tid + (slot << 8);

        // warp argmax: dist>=0 so float bits compare as unsigned; ~idx max = min idx
        unsigned hv   = __float_as_uint(bv);
        unsigned m    = __reduce_max_sync(0xffffffffu, hv);
        unsigned cand = (hv == m) ? ~(unsigned)bi : 0u;
        unsigned l2   = __reduce_max_sync(0xffffffffu, cand);

        int buf = it & 1;
        if (lane == 0) { svh[buf][w] = m; svl[buf][w] = l2; }
        __syncthreads();

        unsigned hi = (lane < 8) ? svh[buf][lane] : 0u;
        unsigned lo = (lane < 8) ? svl[buf][lane] : 0u;
        unsigned M  = __reduce_max_sync(0xffffffffu, hi);
        unsigned c2 = (hi == M) ? lo : 0u;
        unsigned L  = __reduce_max_sync(0xffffffffu, c2);
        far = (int)~L;
    }
}

// ============ LAUNCH 2: ballq (blocks 0..511) + gemm (blocks 512..1535) ============
__global__ void __launch_bounds__(512) ballq_gemm_kernel(
        const float* __restrict__ xyz, const float* __restrict__ points) {
    extern __shared__ __align__(16) char SM[];
    const int bid = blockIdx.x;
    const int tid = threadIdx.x;

    if (bid < NB_BALLQ) {
        // -------- ball query: one warp per center, ordered scan + early exit ------
        float* xs = (float*)SM;
        float* ys = xs + NN;
        float* zs = ys + NN;

        const int b  = bid >> 6;            // 64 blocks per batch
        const int s0 = (bid & 63) * 16;

        const float* xb = xyz + (size_t)b * NN * 3;
        for (int k = tid; k < NN * 3; k += 512) {
            float v = xb[k];
            int i = k / 3, c = k - 3 * i;
            if (c == 0) xs[i] = v; else if (c == 1) ys[i] = v; else zs[i] = v;
        }
        __syncthreads();

        const int warp = tid >> 5, lane = tid & 31;
        const int s = s0 + warp;
        const float* cp = d_newxyz + ((size_t)b * SS + s) * 3;
        const float cx = __ldg(cp + 0), cy = __ldg(cp + 1), cz = __ldg(cp + 2);
        const int base = (b * SS + s) * NSAMP;
        const float r2 = 0.15f * 0.15f;

        int count = 0, first = 0;
        for (int ci = 0; ci < NN / 32; ci++) {
            int i = ci * 32 + lane;
            float dx = cx - xs[i], dy = cy - ys[i], dz = cz - zs[i];
            float d = dx * dx + dy * dy + dz * dz;
            bool hit = (d <= r2);
            unsigned m = __ballot_sync(0xffffffffu, hit);
            if (m) {
                if (count == 0) first = __shfl_sync(0xffffffffu, i, __ffs(m) - 1);
                int nh   = __popc(m);
                int take = min(nh, NSAMP - count);
                int pos  = __popc(m & ((1u << lane) - 1u));
                if (hit && pos < take) {
                    d_gidx[base + count + pos] = i;
                    atomicAdd(&d_cnt[b * NN + i], 1);
                }
                count += take;
                if (count >= NSAMP) break;
            }
        }
        if (lane >= count) {   // pad with first in-radius index
            d_gidx[base + lane] = first;
            atomicAdd(&d_cnt[b * NN + first], 1);
        }
        return;
    }

    // -------- GEMM: g = points @ Wf + bf (validated 512-thread body) ------
    {
        float*  sP = (float*)SM;                  // [64][64]  16KB
        float4* sW = (float4*)(SM + 16384);       // [64][32]  32KB

        const int gi   = bid - NB_BALLQ;
        const int row0 = (gi >> 1) * 64;
        const int cb   = (gi & 1) * 128;

        const float4* Pq = (const float4*)(points + (size_t)row0 * CIN);
        ((float4*)sP)[tid]       = Pq[tid];
        ((float4*)sP)[tid + 512] = Pq[tid + 512];

        const float4* Wq = (const float4*)d_Wf;   // 64 quads per k-row
#pragma unroll
        for (int t = tid; t < CIN * 32; t += 512) {
            int k = t >> 5, q = t & 31;
            sW[t] = Wq[k * 64 + (cb >> 2) + q];
        }
        __syncthreads();

        const int w = tid >> 5, lane = tid & 31;
        const int r0 = w * 4;                     // 16 warps x 4 rows = 64

        float4 acc[4];
        float4 bias = *(const float4*)(d_bf + cb + lane * 4);
#pragma unroll
        for (int i = 0; i < 4; i++) acc[i] = bias;

#pragma unroll
        for (int k = 0; k < CIN; k += 4) {
            float pr[4][4];
#pragma unroll
            for (int i = 0; i < 4; i++) {
                float4 t = *(const float4*)&sP[(r0 + i) * CIN + k];
                pr[i][0] = t.x; pr[i][1] = t.y; pr[i][2] = t.z; pr[i][3] = t.w;
            }
#pragma unroll
            for (int kk = 0; kk < 4; kk++) {
                float4 wv = sW[(k + kk) * 32 + lane];
#pragma unroll
                for (int i = 0; i < 4; i++) {
                    acc[i].x += pr[i][kk] * wv.x;
                    acc[i].y += pr[i][kk] * wv.y;
                    acc[i].z += pr[i][kk] * wv.z;
                    acc[i].w += pr[i][kk] * wv.w;
                }
            }
        }
#pragma unroll
        for (int i = 0; i < 4; i++)
            *(float4*)(d_g + (size_t)(row0 + r0 + i) * COUT + cb + lane * 4) = acc[i];
    }
}

// ---------------- BN statistics via per-point counts ----------------
__global__ void __launch_bounds__(256) stats_kernel() {
    const int c    = threadIdx.x;
    const int row0 = blockIdx.x * 128;
    __shared__ float wcnt[128];
    if (threadIdx.x < 128) wcnt[threadIdx.x] = (float)d_cnt[row0 + threadIdx.x];
    __syncthreads();
    float s = 0.f, q = 0.f;
    for (int r = 0; r < 128; r++) {
        float w = wcnt[r];
        if (w != 0.f) {
            float v = d_g[(size_t)(row0 + r) * COUT + c];
            float wvv = w * v;
            s += wvv;
            q += wvv * v;
        }
    }
    atomicAdd(&d_sum[c], s);
    atomicAdd(&d_sumsq[c], q);
}

// ---------------- gather + BN + ReLU + max-pool (BN affine per block) ------
__global__ void __launch_bounds__(256) final_kernel(
        const float* __restrict__ gamma, const float* __restrict__ beta,
        float* __restrict__ out) {
    const int b = blockIdx.y, s = blockIdx.x, c = threadIdx.x;
    __shared__ int idx[NSAMP];
    if (c < NSAMP) idx[c] = d_gidx[(b * SS + s) * NSAMP + c];
    __syncthreads();
    const float* gb = d_g + (size_t)b * NN * COUT + c;
    float mx = -1e30f, mn = 1e30f;
#pragma unroll
    for (int n = 0; n < NSAMP; n++) {
        float v = gb[(size_t)idx[n] * COUT];
        mx = fmaxf(mx, v);
        mn = fminf(mn, v);
    }
    const float M = (float)(BB * SS * NSAMP);
    float mean = d_sum[c] / M;
    float var  = fmaxf(d_sumsq[c] / M - mean * mean, 0.f);
    float a    = gamma[c] / sqrtf(var + 1e-5f);
    float bb2  = beta[c] - mean * a;
    float m = (a >= 0.f) ? mx : mn;     // relu(a*max+b) = max relu(a*h+b), monotone
    out[((size_t)(b * SS + s)) * COUT + c] = fmaxf(a * m + bb2, 0.f);
}

// ---------------- launch (single stream; graph-capture safe) ----------------
extern "C" void kernel_launch(void* const* d_in, const int* in_sizes, int n_in,
                              void* d_out, int out_size) {
    const float* xyz    = (const float*)d_in[0];
    // d_in[1] = t : unused by reference
    const float* points = (const float*)d_in[2];
    const float* W1     = (const float*)d_in[3];
    const float* b1     = (const float*)d_in[4];
    const float* Wc     = (const float*)d_in[5];
    const float* bc     = (const float*)d_in[6];
    const float* gamma  = (const float*)d_in[7];
    const float* beta   = (const float*)d_in[8];
    float* out = (float*)d_out;

    // fps_prep: 48KB dynamic + small static smem -> raise per-function cap
    // (validated mechanism: round 8)
    cudaFuncSetAttribute(fps_prep_kernel,
                         cudaFuncAttributeMaxDynamicSharedMemorySize, 64 * 1024);

    fps_prep_kernel<<<GRID_FP, 256, FPS_SMEM>>>(xyz, W1, b1, Wc, bc);
    ballq_gemm_kernel<<<GRID_BG, 512, NN * 3 * sizeof(float)>>>(xyz, points);
    stats_kernel<<<(BB * NN) / 128, 256>>>();
    final_kernel<<<dim3(SS, BB), 256>>>(gamma, beta, out);
}